// round 1
// baseline (speedup 1.0000x reference)
#include <cuda_runtime.h>
#include <float.h>

#define Bb 4
#define Cc 256
#define C8 32
#define Hh 64
#define Ww 64
#define HW 4096

// ---------------- scratch (static device arrays; no runtime allocation) ----
__device__ float g_q[Bb * C8 * HW];           // 2 MB
__device__ float g_k[Bb * C8 * HW];           // 2 MB
__device__ float g_v[Bb * Cc * HW];           // 16 MB
__device__ float g_T[Bb * Cc * HW];           // 16 MB
__device__ float g_Wt[2 * Cc * 9 * Cc];       // 4.7 MB  (I=512,3,3,O=256)
__device__ float g_pmax[Bb * 4 * HW];
__device__ int   g_parg[Bb * 4 * HW];
__device__ float g_S[Bb * HW];
__device__ int   g_arg[Bb * HW];

// ---------------- 0) weight transpose: Wf(O=256,I=512,3,3) -> Wt(I,3,3,O) ---
__global__ void transpose_wf(const float* __restrict__ Wf) {
    int t = blockIdx.x * 256 + threadIdx.x;       // 512*9*256 = 1,179,648
    if (t >= 512 * 9 * 256) return;
    int o = t & 255;
    int k = (t >> 8) % 9;
    int i = t / (256 * 9);
    g_Wt[t] = Wf[((size_t)o * 512 + i) * 9 + k];
}

// ---------------- 1) generic 1x1-conv GEMM: out[b,o,hw] = W[o,:]@x[b,:,hw]+bias
// tile: 32 o x 128 hw per block, 256 threads, thread tile 4o x 4hw, K-chunk 16
__global__ __launch_bounds__(256) void gemm1x1(const float* __restrict__ X,
                                               const float* __restrict__ Wm,
                                               const float* __restrict__ bias,
                                               float* __restrict__ out, int O) {
    __shared__ float Xs[16][128];
    __shared__ float Ws[16][33];
    const int b   = blockIdx.z;
    const int o0  = blockIdx.y * 32;
    const int hw0 = blockIdx.x * 128;
    const int tid = threadIdx.x;
    const int hid = tid & 31;   // hw lane
    const int oid = tid >> 5;   // 0..7

    const float* xb = X + (size_t)b * Cc * HW;
    float acc[4][4];
#pragma unroll
    for (int n = 0; n < 4; n++)
#pragma unroll
        for (int m = 0; m < 4; m++) acc[n][m] = 0.f;

    for (int c0 = 0; c0 < Cc; c0 += 16) {
        __syncthreads();
#pragma unroll
        for (int r = 0; r < 8; r++) {            // 16*128/256 = 8 per thread
            int idx = tid + r * 256;
            int cc = idx >> 7, h = idx & 127;
            Xs[cc][h] = xb[(size_t)(c0 + cc) * HW + hw0 + h];
        }
#pragma unroll
        for (int r = 0; r < 2; r++) {            // 16*32/256 = 2 per thread
            int idx = tid + r * 256;
            int cc = idx >> 5, o = idx & 31;
            Ws[cc][o] = Wm[(size_t)(o0 + o) * Cc + c0 + cc];
        }
        __syncthreads();
#pragma unroll
        for (int cc = 0; cc < 16; cc++) {
            float wv[4], xv[4];
#pragma unroll
            for (int n = 0; n < 4; n++) wv[n] = Ws[cc][oid + 8 * n];
#pragma unroll
            for (int m = 0; m < 4; m++) xv[m] = Xs[cc][hid + 32 * m];
#pragma unroll
            for (int n = 0; n < 4; n++)
#pragma unroll
                for (int m = 0; m < 4; m++) acc[n][m] += wv[n] * xv[m];
        }
    }
#pragma unroll
    for (int n = 0; n < 4; n++) {
        int o = o0 + oid + 8 * n;
        float bi = bias[o];
#pragma unroll
        for (int m = 0; m < 4; m++) {
            int hw = hw0 + hid + 32 * m;
            out[(size_t)b * O * HW + (size_t)o * HW + hw] = acc[n][m] + bi;
        }
    }
}

// ---------------- 2) fused energy rowmax/argmax --------------------------
// energy[b,i,j] = sum_c k[b,c,i]*q[b,c,j]; per query j: max/argmax over i.
// grid (jtile=32, b=4, split=4); block 128 (one query per thread); keys split 4x.
__global__ __launch_bounds__(128) void energy_argmax() {
    __shared__ float ks[32][128];
    const int b  = blockIdx.y;
    const int j  = blockIdx.x * 128 + threadIdx.x;
    const int sp = blockIdx.z;
    const float* qb = g_q + (size_t)b * C8 * HW;
    const float* kb = g_k + (size_t)b * C8 * HW;

    float qr[32];
#pragma unroll
    for (int c = 0; c < 32; c++) qr[c] = qb[c * HW + j];

    float best = -FLT_MAX;
    int   barg = 0;
    const int i0base = sp * 1024;

    for (int it = 0; it < 8; it++) {
        int i0 = i0base + it * 128;
        __syncthreads();
#pragma unroll
        for (int c = 0; c < 32; c++) ks[c][threadIdx.x] = kb[c * HW + i0 + threadIdx.x];
        __syncthreads();
#pragma unroll 4
        for (int ii = 0; ii < 128; ii += 4) {
            float a0 = 0.f, a1 = 0.f, a2 = 0.f, a3 = 0.f;
#pragma unroll
            for (int c = 0; c < 32; c++) {
                float4 kv = *(const float4*)&ks[c][ii];
                a0 += kv.x * qr[c];
                a1 += kv.y * qr[c];
                a2 += kv.z * qr[c];
                a3 += kv.w * qr[c];
            }
            if (a0 > best) { best = a0; barg = i0 + ii; }
            if (a1 > best) { best = a1; barg = i0 + ii + 1; }
            if (a2 > best) { best = a2; barg = i0 + ii + 2; }
            if (a3 > best) { best = a3; barg = i0 + ii + 3; }
        }
    }
    g_pmax[((size_t)b * 4 + sp) * HW + j] = best;
    g_parg[((size_t)b * 4 + sp) * HW + j] = barg;
}

// ---------------- 3) reduce the 4 key-splits (keeps lowest index on ties) --
__global__ void reduce_argmax() {
    int t = blockIdx.x * 256 + threadIdx.x;       // 16384
    if (t >= Bb * HW) return;
    int b = t >> 12, j = t & 4095;
    float best = g_pmax[((size_t)b * 4) * HW + j];
    int   arg  = g_parg[((size_t)b * 4) * HW + j];
#pragma unroll
    for (int sp = 1; sp < 4; sp++) {
        float e = g_pmax[((size_t)b * 4 + sp) * HW + j];
        if (e > best) { best = e; arg = g_parg[((size_t)b * 4 + sp) * HW + j]; }
    }
    g_S[t] = best;
    g_arg[t] = arg;
}

// ---------------- 4) gather T[b,c,p] = v[b,c,arg[b,p]] ---------------------
__global__ void gather_T() {
    int p = blockIdx.x * 256 + threadIdx.x;
    int c = blockIdx.y, b = blockIdx.z;
    int a = g_arg[b * HW + p];
    g_T[((size_t)b * Cc + c) * HW + p] = g_v[((size_t)b * Cc + c) * HW + a];
}

// ---------------- 5) conv3x3 over cat(front_x, T) + epilogue ---------------
// block: 64 output channels x 16x16 spatial, 256 threads, thread tile 8o x 8s.
__global__ __launch_bounds__(256, 2) void conv3x3_epi(const float* __restrict__ front_x,
                                                      const float* __restrict__ bf,
                                                      float* __restrict__ out) {
    __shared__ float in_s[4][18][18];
    __shared__ float w_s[4 * 9 * 64];
    __shared__ float S_s[256];

    const int b   = blockIdx.z;
    const int o0  = blockIdx.y * 64;
    const int st  = blockIdx.x;                  // 16 spatial tiles
    const int y0  = (st >> 2) * 16;
    const int x0  = (st & 3) * 16;
    const int tid = threadIdx.x;
    const int sid = tid & 31;                    // spatial lane
    const int oid = tid >> 5;                    // 0..7
    const int srow = sid >> 4;                   // 0/1
    const int scol = sid & 15;

    if (tid < 256) {
        int ry = tid >> 4, rx = tid & 15;
        S_s[tid] = g_S[(size_t)b * HW + (y0 + ry) * Ww + x0 + rx];
    }

    float acc[8][8];
#pragma unroll
    for (int n = 0; n < 8; n++)
#pragma unroll
        for (int m = 0; m < 8; m++) acc[n][m] = 0.f;

    for (int ci0 = 0; ci0 < 512; ci0 += 4) {
        __syncthreads();
        // input tile 4 x 18 x 18, zero-padded
        for (int idx = tid; idx < 4 * 324; idx += 256) {
            int cil = idx / 324, rem = idx % 324;
            int r = rem / 18, cc = rem % 18;
            int ci = ci0 + cil;
            int y = y0 + r - 1, x = x0 + cc - 1;
            float v = 0.f;
            if (y >= 0 && y < Hh && x >= 0 && x < Ww) {
                const float* s = (ci < 256)
                    ? (front_x + ((size_t)b * Cc + ci) * HW)
                    : (g_T + ((size_t)b * Cc + (ci - 256)) * HW);
                v = s[y * Ww + x];
            }
            in_s[cil][r][cc] = v;
        }
        // weights (pre-transposed, coalesced): Wt[ci][k][o]
#pragma unroll
        for (int r = 0; r < 9; r++) {            // 4*9*64/256 = 9 per thread
            int idx = tid + r * 256;
            w_s[idx] = g_Wt[(size_t)(ci0 + (idx >> 6) / 9) * 9 * 256
                            + ((idx >> 6) % 9) * 256 + o0 + (idx & 63)];
        }
        __syncthreads();

        for (int cil = 0; cil < 4; cil++) {
#pragma unroll
            for (int k = 0; k < 9; k++) {
                const int ky = k / 3, kx = k % 3;
                float wv[8], iv[8];
#pragma unroll
                for (int n = 0; n < 8; n++) wv[n] = w_s[cil * 576 + k * 64 + oid + 8 * n];
#pragma unroll
                for (int m = 0; m < 8; m++) iv[m] = in_s[cil][srow + 2 * m + ky][scol + kx];
#pragma unroll
                for (int n = 0; n < 8; n++)
#pragma unroll
                    for (int m = 0; m < 8; m++) acc[n][m] += wv[n] * iv[m];
            }
        }
    }

    // epilogue: out = front_x + (conv + bf) * S
    float Sv[8];
#pragma unroll
    for (int m = 0; m < 8; m++) Sv[m] = S_s[(srow + 2 * m) * 16 + scol];
#pragma unroll
    for (int n = 0; n < 8; n++) {
        int o = o0 + oid + 8 * n;
        float bi = bf[o];
#pragma unroll
        for (int m = 0; m < 8; m++) {
            int y = y0 + srow + 2 * m;
            int x = x0 + scol;
            size_t off = ((size_t)b * Cc + o) * HW + y * Ww + x;
            out[off] = front_x[off] + (acc[n][m] + bi) * Sv[m];
        }
    }
}

// ---------------- launch --------------------------------------------------
extern "C" void kernel_launch(void* const* d_in, const int* in_sizes, int n_in,
                              void* d_out, int out_size) {
    const float* front_x     = (const float*)d_in[0];
    const float* cross_x     = (const float*)d_in[1];
    const float* front_x_hat = (const float*)d_in[2];
    const float* Wq = (const float*)d_in[3];
    const float* bq = (const float*)d_in[4];
    const float* Wk = (const float*)d_in[5];
    const float* bk = (const float*)d_in[6];
    const float* Wv = (const float*)d_in[7];
    const float* bv = (const float*)d_in[8];
    const float* Wf = (const float*)d_in[9];
    const float* bf = (const float*)d_in[10];
    float* out = (float*)d_out;

    float *q, *k, *v;
    cudaGetSymbolAddress((void**)&q, g_q);
    cudaGetSymbolAddress((void**)&k, g_k);
    cudaGetSymbolAddress((void**)&v, g_v);

    transpose_wf<<<4608, 256>>>(Wf);

    gemm1x1<<<dim3(32, 1, 4), 256>>>(cross_x,     Wq, bq, q, C8);   // q
    gemm1x1<<<dim3(32, 1, 4), 256>>>(front_x,     Wk, bk, k, C8);   // k
    gemm1x1<<<dim3(32, 8, 4), 256>>>(front_x_hat, Wv, bv, v, Cc);   // v

    energy_argmax<<<dim3(32, 4, 4), 128>>>();
    reduce_argmax<<<64, 256>>>();
    gather_T<<<dim3(16, 256, 4), 256>>>();

    conv3x3_epi<<<dim3(16, 4, 4), 256>>>(front_x, bf, out);
}